// round 14
// baseline (speedup 1.0000x reference)
#include <cuda_runtime.h>
#include <cstdint>

// Problem constants
#define Bn   4
#define Cn   16
#define Hn   800
#define Wn   1200
#define HWn  (Hn * Wn)          // 960000
#define HFn  200                 // H/4
#define WFn  200                 // W/6
#define NPIX (512 * 512)         // 262144

// Part -> source selection: parts {1, 14..21} come from source_feature
#define SRC_MASK 0x003FC002u
// Apparel classes: cls==2 or 15<=cls<=22  -> bits 2, 15..22
#define APP_MASK 0x007F8004u

// XLA lowering of (x*199)/255: divide -> multiply by fl(1/255) = 0x3B808081,
// multiplies NOT reassociated (verified bit-exact in R3).
__device__ __forceinline__ float recip255() {
    return __uint_as_float(0x3B808081u);
}

// ---------------------------------------------------------------------------
// Single-kernel channel-split gather with inline smem-staged decode.
//   gridDim = (NPIX/256, B, 5):
//     z=0..3 : 4 feature channels each (per-group gather footprint ~60MB
//              across batches -> L2-resident, reuse captured)
//     z=4    : texture/composite channels 16..18 (light group)
//   dense_pose is staged through shared memory as 192 coalesced float4 loads
//   per block (48 sectors vs 288 for naive stride-12B scalar reads).
//   No scratch, no pre-pass.
// ---------------------------------------------------------------------------
__global__ __launch_bounds__(256) void k_split(
    const float* __restrict__ sf,    // source_feature [B,16,H,W]
    const float* __restrict__ tf,    // target_feature [B,16,H,W]
    const float* __restrict__ dp,    // dense_pose [B,512,512,3]
    const float* __restrict__ st,    // source_texture [B,3,H,W]
    const float* __restrict__ timg,  // target_image [B,3,512,512]
    float* __restrict__ out)         // [B,19,512,512]
{
    __shared__ float s[768];         // 256 pixels * 3 floats

    const int b    = blockIdx.y;
    const int g    = blockIdx.z;                    // 0..4
    const int tid  = threadIdx.x;
    const int base = blockIdx.x * 256;
    const int pix  = base + tid;

    // Coalesced dp staging: 768 floats = 192 float4 (3072 B, 16B-aligned)
    const float4* src = reinterpret_cast<const float4*>(
        dp + ((size_t)b * NPIX + base) * 3);
    if (tid < 192)
        reinterpret_cast<float4*>(s)[tid] = src[tid];
    __syncthreads();

    const float clsf = s[tid * 3 + 0];
    const float U    = s[tid * 3 + 1];
    const float V    = s[tid * 3 + 2];

    const int  cls   = (int)clsf;
    const bool valid = (cls >= 1) && (V != 0.0f);

    int p = cls - 1;
    p = p < 0 ? 0 : (p > 23 ? 23 : p);

    const float R = recip255();
    // XLA: t = RN(x*199); idx = trunc(RN(t * fl(1/255)))
    const int ui = (int)__fmul_rn(__fmul_rn(U, 199.0f), R);
    const int vi = (int)__fmul_rn(__fmul_rn(__fsub_rn(255.0f, V), 199.0f), R);

    const int tr  = p / 6;
    const int tc  = p - tr * 6;
    const int pos = (tr * HFn + ui) * Wn + (tc * WFn + vi);

    if (g < 4) {
        const bool use_src = (SRC_MASK >> p) & 1u;
        const int  ch0     = g * 4;
        const float* fbase = (use_src ? sf : tf)
                           + (size_t)b * Cn * HWn + (size_t)ch0 * HWn + pos;

        float v[4];
        if (valid) {
#pragma unroll
            for (int c = 0; c < 4; c++)
                v[c] = __ldg(fbase + (size_t)c * HWn);
        } else {
#pragma unroll
            for (int c = 0; c < 4; c++)
                v[c] = 0.0f;
        }

        float* ob = out + (size_t)b * 19 * NPIX + (size_t)ch0 * NPIX + pix;
#pragma unroll
        for (int c = 0; c < 4; c++)
            ob[(size_t)c * NPIX] = v[c];
    } else {
        const bool apparel = (APP_MASK >> cls) & 1u;   // implies cls != 0
        const bool bg      = (cls != 0);

        float* oc = out + (size_t)b * 19 * NPIX + 16 * NPIX + pix;
        if (apparel) {
            float t0 = 0.f, t1 = 0.f, t2 = 0.f;
            if (valid) {
                const float* tb = st + (size_t)b * 3 * HWn + pos;
                t0 = __ldg(tb);
                t1 = __ldg(tb + HWn);
                t2 = __ldg(tb + 2 * HWn);
            }
            oc[0 * NPIX] = t0;
            oc[1 * NPIX] = t1;
            oc[2 * NPIX] = t2;
        } else if (bg) {
            const float* ti = timg + (size_t)b * 3 * NPIX + pix;
            oc[0 * NPIX] = __ldg(ti);
            oc[1 * NPIX] = __ldg(ti + NPIX);
            oc[2 * NPIX] = __ldg(ti + 2 * NPIX);
        } else {
            oc[0 * NPIX] = 0.0f;
            oc[1 * NPIX] = 0.0f;
            oc[2 * NPIX] = 0.0f;
        }
    }
}

// ---------------------------------------------------------------------------
extern "C" void kernel_launch(void* const* d_in, const int* in_sizes, int n_in,
                              void* d_out, int out_size)
{
    const float* source_feature = (const float*)d_in[0];
    const float* target_feature = (const float*)d_in[1];
    const float* dense_pose     = (const float*)d_in[2];
    const float* source_texture = (const float*)d_in[3];
    const float* target_image   = (const float*)d_in[4];
    float* out = (float*)d_out;

    dim3 g(NPIX / 256, Bn, 5);
    k_split<<<g, 256>>>(source_feature, target_feature, dense_pose,
                        source_texture, target_image, out);
}

// round 15
// speedup vs baseline: 1.4501x; 1.4501x over previous
#include <cuda_runtime.h>
#include <cstdint>

// Problem constants
#define Bn   4
#define Cn   16
#define Hn   800
#define Wn   1200
#define HWn  (Hn * Wn)          // 960000
#define HFn  200                 // H/4
#define WFn  200                 // W/6
#define NPIX (512 * 512)         // 262144

// Part -> source selection: parts {1, 14..21} come from source_feature
#define SRC_MASK 0x003FC002u
// Apparel classes: cls==2 or 15<=cls<=22  -> bits 2, 15..22
#define APP_MASK 0x007F8004u

// XLA lowering of (x*199)/255: divide -> multiply by fl(1/255) = 0x3B808081,
// multiplies NOT reassociated (verified bit-exact in R3).
__device__ __forceinline__ float recip255() {
    return __uint_as_float(0x3B808081u);
}

// ---------------------------------------------------------------------------
// Channel-split fused gather, balanced groups (R10 + tail fix):
//   gridDim = (NPIX/256, B, 4). Group g gathers feature channels 4g..4g+3.
//   Groups 0..2 ALSO each produce one composite channel (16+g): the
//   apparel/bg/zero select is per-channel separable, so the texture gather
//   and timg read split cleanly. Load balance {5,5,5,4} vs R10's {4,4,4,7}.
//   Decode is inline with plain scalar dp loads (R14 showed smem staging
//   costs more L1tex-pipe work than it saves). No scratch, single launch.
// ---------------------------------------------------------------------------
__global__ __launch_bounds__(256) void k_split(
    const float* __restrict__ sf,    // source_feature [B,16,H,W]
    const float* __restrict__ tf,    // target_feature [B,16,H,W]
    const float* __restrict__ dp,    // dense_pose [B,512,512,3]
    const float* __restrict__ st,    // source_texture [B,3,H,W]
    const float* __restrict__ timg,  // target_image [B,3,512,512]
    float* __restrict__ out)         // [B,19,512,512]
{
    const int b   = blockIdx.y;
    const int g   = blockIdx.z;                      // 0..3
    const int pix = blockIdx.x * 256 + threadIdx.x;  // 0 .. NPIX-1

    const float* d = dp + ((size_t)b * NPIX + pix) * 3;
    const float clsf = d[0];
    const float U    = d[1];
    const float V    = d[2];

    const int  cls   = (int)clsf;
    const bool valid = (cls >= 1) && (V != 0.0f);

    int p = cls - 1;
    p = p < 0 ? 0 : (p > 23 ? 23 : p);

    const float R = recip255();
    // XLA: t = RN(x*199); idx = trunc(RN(t * fl(1/255)))
    const int ui = (int)__fmul_rn(__fmul_rn(U, 199.0f), R);
    const int vi = (int)__fmul_rn(__fmul_rn(__fsub_rn(255.0f, V), 199.0f), R);

    const int tr  = p / 6;
    const int tc  = p - tr * 6;
    const int pos = (tr * HFn + ui) * Wn + (tc * WFn + vi);

    const bool use_src = (SRC_MASK >> p) & 1u;
    const int  ch0     = g * 4;
    const float* fbase = (use_src ? sf : tf)
                       + (size_t)b * Cn * HWn + (size_t)ch0 * HWn + pos;

    // 4 feature channel gathers
    float v[4];
    if (valid) {
#pragma unroll
        for (int c = 0; c < 4; c++)
            v[c] = __ldg(fbase + (size_t)c * HWn);
    } else {
#pragma unroll
        for (int c = 0; c < 4; c++)
            v[c] = 0.0f;
    }

    float* ob = out + (size_t)b * 19 * NPIX + (size_t)ch0 * NPIX + pix;
#pragma unroll
    for (int c = 0; c < 4; c++)
        ob[(size_t)c * NPIX] = v[c];

    // Groups 0..2: one composite channel each (out channel 16+g)
    if (g < 3) {
        const bool apparel = (APP_MASK >> cls) & 1u;   // implies cls != 0
        const bool bg      = (cls != 0);

        float oc;
        if (apparel) {
            oc = valid ? __ldg(st + (size_t)b * 3 * HWn + (size_t)g * HWn + pos)
                       : 0.0f;
        } else if (bg) {
            oc = __ldg(timg + (size_t)b * 3 * NPIX + (size_t)g * NPIX + pix);
        } else {
            oc = 0.0f;
        }
        out[(size_t)b * 19 * NPIX + (size_t)(16 + g) * NPIX + pix] = oc;
    }
}

// ---------------------------------------------------------------------------
extern "C" void kernel_launch(void* const* d_in, const int* in_sizes, int n_in,
                              void* d_out, int out_size)
{
    const float* source_feature = (const float*)d_in[0];
    const float* target_feature = (const float*)d_in[1];
    const float* dense_pose     = (const float*)d_in[2];
    const float* source_texture = (const float*)d_in[3];
    const float* target_image   = (const float*)d_in[4];
    float* out = (float*)d_out;

    dim3 g(NPIX / 256, Bn, 4);
    k_split<<<g, 256>>>(source_feature, target_feature, dense_pose,
                        source_texture, target_image, out);
}

// round 16
// speedup vs baseline: 1.5201x; 1.0483x over previous
#include <cuda_runtime.h>
#include <cstdint>

// Problem constants
#define Bn   4
#define Cn   16
#define Hn   800
#define Wn   1200
#define HWn  (Hn * Wn)          // 960000
#define HFn  200                 // H/4
#define WFn  200                 // W/6
#define NPIX (512 * 512)         // 262144

// Part -> source selection: parts {1, 14..21} come from source_feature
#define SRC_MASK 0x003FC002u
// Apparel classes: cls==2 or 15<=cls<=22  -> bits 2, 15..22
#define APP_MASK 0x007F8004u

// XLA lowering of (x*199)/255: divide -> multiply by fl(1/255) = 0x3B808081,
// multiplies NOT reassociated (verified bit-exact in R3).
__device__ __forceinline__ float recip255() {
    return __uint_as_float(0x3B808081u);
}

struct Pix {
    int  pos;
    bool valid, use_src, apparel, bg;
};

__device__ __forceinline__ Pix decode1(float clsf, float U, float V)
{
    const int cls = (int)clsf;
    Pix o;
    o.valid   = (cls >= 1) && (V != 0.0f);
    o.apparel = (APP_MASK >> cls) & 1u;
    o.bg      = (cls != 0);

    int p = cls - 1;
    p = p < 0 ? 0 : (p > 23 ? 23 : p);
    o.use_src = (SRC_MASK >> p) & 1u;

    const float R = recip255();
    // XLA: t = RN(x*199); idx = trunc(RN(t * fl(1/255)))
    const int ui = (int)__fmul_rn(__fmul_rn(U, 199.0f), R);
    const int vi = (int)__fmul_rn(__fmul_rn(__fsub_rn(255.0f, V), 199.0f), R);

    const int tr = p / 6;
    const int tc = p - tr * 6;
    o.pos = (tr * HFn + ui) * Wn + (tc * WFn + vi);
    return o;
}

// ---------------------------------------------------------------------------
// Channel-split fused gather, 4 consecutive pixels per thread:
//   - dense_pose decode: 3 float4 loads per thread (4x fewer L1 lines than
//     scalar stride-12B reads), decoded inline; paid once per group.
//   - feature gathers stay scalar random (irreducible), 16 per thread within
//     ONE channel group (L2-resident footprint preserved).
//   - all output stores are float4 (fewer instructions through L1tex pipe).
//   gridDim = (NPIX/1024, B, 4); groups 0..2 also own composite ch 16+g.
// ---------------------------------------------------------------------------
__global__ __launch_bounds__(256) void k_split4(
    const float* __restrict__ sf,    // source_feature [B,16,H,W]
    const float* __restrict__ tf,    // target_feature [B,16,H,W]
    const float* __restrict__ dp,    // dense_pose [B,512,512,3]
    const float* __restrict__ st,    // source_texture [B,3,H,W]
    const float* __restrict__ timg,  // target_image [B,3,512,512]
    float* __restrict__ out)         // [B,19,512,512]
{
    const int b    = blockIdx.y;
    const int g    = blockIdx.z;                         // 0..3
    const int pix0 = blockIdx.x * 1024 + threadIdx.x * 4;

    // 12 floats of dense_pose for 4 pixels, via 3 float4 loads (16B aligned)
    const float4* dsrc = reinterpret_cast<const float4*>(
        dp + ((size_t)b * NPIX + pix0) * 3);
    const float4 A = dsrc[0];
    const float4 Bq = dsrc[1];
    const float4 Cq = dsrc[2];

    Pix px[4];
    px[0] = decode1(A.x,  A.y,  A.z);
    px[1] = decode1(A.w,  Bq.x, Bq.y);
    px[2] = decode1(Bq.z, Bq.w, Cq.x);
    px[3] = decode1(Cq.y, Cq.z, Cq.w);

    const int ch0 = g * 4;
    const size_t fb = (size_t)b * Cn * HWn + (size_t)ch0 * HWn;

    // 16 random gather loads (4 channels x 4 pixels), issued back to back
    float v[4][4];   // v[pixel][channel]
#pragma unroll
    for (int i = 0; i < 4; i++) {
        const float* fbase = (px[i].use_src ? sf : tf) + fb + px[i].pos;
        if (px[i].valid) {
#pragma unroll
            for (int c = 0; c < 4; c++)
                v[i][c] = __ldg(fbase + (size_t)c * HWn);
        } else {
#pragma unroll
            for (int c = 0; c < 4; c++)
                v[i][c] = 0.0f;
        }
    }

    // float4 stores: one per channel covering the 4 consecutive pixels
    float* ob = out + (size_t)b * 19 * NPIX + (size_t)ch0 * NPIX + pix0;
#pragma unroll
    for (int c = 0; c < 4; c++) {
        float4 w = make_float4(v[0][c], v[1][c], v[2][c], v[3][c]);
        *reinterpret_cast<float4*>(ob + (size_t)c * NPIX) = w;
    }

    // Groups 0..2: composite channel 16+g for the 4 pixels
    if (g < 3) {
        // coalesced float4 read of target_image channel g
        const float4 ti = *reinterpret_cast<const float4*>(
            timg + (size_t)b * 3 * NPIX + (size_t)g * NPIX + pix0);
        const float tiv[4] = { ti.x, ti.y, ti.z, ti.w };

        float oc[4];
#pragma unroll
        for (int i = 0; i < 4; i++) {
            if (px[i].apparel) {
                oc[i] = px[i].valid
                      ? __ldg(st + (size_t)b * 3 * HWn + (size_t)g * HWn + px[i].pos)
                      : 0.0f;
            } else if (px[i].bg) {
                oc[i] = tiv[i];
            } else {
                oc[i] = 0.0f;
            }
        }
        *reinterpret_cast<float4*>(
            out + (size_t)b * 19 * NPIX + (size_t)(16 + g) * NPIX + pix0) =
            make_float4(oc[0], oc[1], oc[2], oc[3]);
    }
}

// ---------------------------------------------------------------------------
extern "C" void kernel_launch(void* const* d_in, const int* in_sizes, int n_in,
                              void* d_out, int out_size)
{
    const float* source_feature = (const float*)d_in[0];
    const float* target_feature = (const float*)d_in[1];
    const float* dense_pose     = (const float*)d_in[2];
    const float* source_texture = (const float*)d_in[3];
    const float* target_image   = (const float*)d_in[4];
    float* out = (float*)d_out;

    dim3 g(NPIX / 1024, Bn, 4);
    k_split4<<<g, 256>>>(source_feature, target_feature, dense_pose,
                         source_texture, target_image, out);
}

// round 17
// speedup vs baseline: 1.5582x; 1.0251x over previous
#include <cuda_runtime.h>
#include <cstdint>

// Problem constants
#define Bn   4
#define Cn   16
#define Hn   800
#define Wn   1200
#define HWn  (Hn * Wn)          // 960000
#define HFn  200                 // H/4
#define WFn  200                 // W/6
#define NPIX (512 * 512)         // 262144

// Part -> source selection: parts {1, 14..21} come from source_feature
#define SRC_MASK 0x003FC002u
// Apparel classes: cls==2 or 15<=cls<=22  -> bits 2, 15..22
#define APP_MASK 0x007F8004u

// Packed decode layout (one uint32 per pixel)
#define POS_MASK    0x000FFFFFu
#define BIT_VALID   (1u << 20)
#define BIT_APPAREL (1u << 21)
#define BIT_BG      (1u << 22)
#define BIT_SRC     (1u << 23)

// XLA lowering of (x*199)/255: divide -> multiply by fl(1/255) = 0x3B808081,
// multiplies NOT reassociated (verified bit-exact in R3).
__device__ __forceinline__ float recip255() {
    return __uint_as_float(0x3B808081u);
}

// Decode one dense_pose triple into a packed uint32 (pos + flags).
__device__ __forceinline__ unsigned int decode1(float clsf, float U, float V)
{
    const int cls = (int)clsf;

    int p = cls - 1;
    p = p < 0 ? 0 : (p > 23 ? 23 : p);

    const float R = recip255();
    // XLA: t = RN(x*199); idx = trunc(RN(t * fl(1/255)))
    const int ui = (int)__fmul_rn(__fmul_rn(U, 199.0f), R);
    const int vi = (int)__fmul_rn(__fmul_rn(__fsub_rn(255.0f, V), 199.0f), R);

    const int tr = p / 6;
    const int tc = p - tr * 6;
    unsigned int packed =
        (unsigned int)((tr * HFn + ui) * Wn + (tc * WFn + vi)) & POS_MASK;

    if ((cls >= 1) && (V != 0.0f))  packed |= BIT_VALID;
    if ((APP_MASK >> cls) & 1u)     packed |= BIT_APPAREL;
    if (cls != 0)                   packed |= BIT_BG;
    if ((SRC_MASK >> p) & 1u)       packed |= BIT_SRC;
    return packed;
}

// ---------------------------------------------------------------------------
// Channel-split fused gather, 4 consecutive pixels per thread, packed decode
// state (1 uint32/pixel) to minimize register pressure -> higher occupancy.
//   gridDim = (NPIX/1024, B, 4); groups 0..2 also own composite ch 16+g.
// ---------------------------------------------------------------------------
__global__ __launch_bounds__(256) void k_split4(
    const float* __restrict__ sf,    // source_feature [B,16,H,W]
    const float* __restrict__ tf,    // target_feature [B,16,H,W]
    const float* __restrict__ dp,    // dense_pose [B,512,512,3]
    const float* __restrict__ st,    // source_texture [B,3,H,W]
    const float* __restrict__ timg,  // target_image [B,3,512,512]
    float* __restrict__ out)         // [B,19,512,512]
{
    const int b    = blockIdx.y;
    const int g    = blockIdx.z;                         // 0..3
    const int pix0 = blockIdx.x * 1024 + threadIdx.x * 4;

    // 12 floats of dense_pose for 4 pixels, via 3 float4 loads (16B aligned)
    const float4* dsrc = reinterpret_cast<const float4*>(
        dp + ((size_t)b * NPIX + pix0) * 3);
    const float4 A  = dsrc[0];
    const float4 Bq = dsrc[1];
    const float4 Cq = dsrc[2];

    unsigned int pk[4];
    pk[0] = decode1(A.x,  A.y,  A.z);
    pk[1] = decode1(A.w,  Bq.x, Bq.y);
    pk[2] = decode1(Bq.z, Bq.w, Cq.x);
    pk[3] = decode1(Cq.y, Cq.z, Cq.w);

    const int ch0 = g * 4;
    const size_t fb = (size_t)b * Cn * HWn + (size_t)ch0 * HWn;

    // 16 random gather loads (4 channels x 4 pixels)
    float v[4][4];   // v[pixel][channel]
#pragma unroll
    for (int i = 0; i < 4; i++) {
        const int pos = (int)(pk[i] & POS_MASK);
        const float* fbase = ((pk[i] & BIT_SRC) ? sf : tf) + fb + pos;
        if (pk[i] & BIT_VALID) {
#pragma unroll
            for (int c = 0; c < 4; c++)
                v[i][c] = __ldg(fbase + (size_t)c * HWn);
        } else {
#pragma unroll
            for (int c = 0; c < 4; c++)
                v[i][c] = 0.0f;
        }
    }

    // float4 stores: one per channel covering the 4 consecutive pixels
    float* ob = out + (size_t)b * 19 * NPIX + (size_t)ch0 * NPIX + pix0;
#pragma unroll
    for (int c = 0; c < 4; c++) {
        float4 w = make_float4(v[0][c], v[1][c], v[2][c], v[3][c]);
        *reinterpret_cast<float4*>(ob + (size_t)c * NPIX) = w;
    }

    // Groups 0..2: composite channel 16+g for the 4 pixels
    if (g < 3) {
        const float4 ti = *reinterpret_cast<const float4*>(
            timg + (size_t)b * 3 * NPIX + (size_t)g * NPIX + pix0);
        const float tiv[4] = { ti.x, ti.y, ti.z, ti.w };

        float oc[4];
#pragma unroll
        for (int i = 0; i < 4; i++) {
            const unsigned int k = pk[i];
            if (k & BIT_APPAREL) {
                oc[i] = (k & BIT_VALID)
                      ? __ldg(st + (size_t)b * 3 * HWn + (size_t)g * HWn
                                 + (int)(k & POS_MASK))
                      : 0.0f;
            } else if (k & BIT_BG) {
                oc[i] = tiv[i];
            } else {
                oc[i] = 0.0f;
            }
        }
        *reinterpret_cast<float4*>(
            out + (size_t)b * 19 * NPIX + (size_t)(16 + g) * NPIX + pix0) =
            make_float4(oc[0], oc[1], oc[2], oc[3]);
    }
}

// ---------------------------------------------------------------------------
extern "C" void kernel_launch(void* const* d_in, const int* in_sizes, int n_in,
                              void* d_out, int out_size)
{
    const float* source_feature = (const float*)d_in[0];
    const float* target_feature = (const float*)d_in[1];
    const float* dense_pose     = (const float*)d_in[2];
    const float* source_texture = (const float*)d_in[3];
    const float* target_image   = (const float*)d_in[4];
    float* out = (float*)d_out;

    dim3 g(NPIX / 1024, Bn, 4);
    k_split4<<<g, 256>>>(source_feature, target_feature, dense_pose,
                         source_texture, target_image, out);
}